// round 16
// baseline (speedup 1.0000x reference)
#include <cuda_runtime.h>

// Soft-argmax: input (B=4, C=14, H=1024, W=1024) fp32 NCHW.
// Output (4, 2, 1024, 1024) fp32.
//
// R12: 256-bit vector loads/stores (ld/st.global.cs.v8.f32, sm_100+ LDG.E.256).
// Each thread processes one 8-float "oct" per channel; per-group (K=7)
// sequential processing keeps peak payload at 56 regs. 128-thread CTAs.

#define HW      (1024 * 1024)
#define HWO     (HW / 8)          // 131072 octs per plane = 2^17
#define HWO_LOG 17
#define C_IN    14
#define K       7
#define B       4

__device__ __forceinline__ void ldg256_cs(const float* __restrict__ p, float* v) {
    asm volatile("ld.global.cs.v8.f32 {%0,%1,%2,%3,%4,%5,%6,%7}, [%8];"
                 : "=f"(v[0]), "=f"(v[1]), "=f"(v[2]), "=f"(v[3]),
                   "=f"(v[4]), "=f"(v[5]), "=f"(v[6]), "=f"(v[7])
                 : "l"(p));
}

__device__ __forceinline__ void stg256_cs(float* __restrict__ p, const float* v) {
    asm volatile("st.global.cs.v8.f32 [%0], {%1,%2,%3,%4,%5,%6,%7,%8};"
                 :: "l"(p),
                    "f"(v[0]), "f"(v[1]), "f"(v[2]), "f"(v[3]),
                    "f"(v[4]), "f"(v[5]), "f"(v[6]), "f"(v[7])
                 : "memory");
}

__device__ __forceinline__ float soft1(float a0, float a1, float a2, float a3,
                                       float a4, float a5, float a6) {
    float e0 = __expf(a0);
    float e1 = __expf(a1);
    float e2 = __expf(a2);
    float e3 = __expf(a3);
    float e4 = __expf(a4);
    float e5 = __expf(a5);
    float e6 = __expf(a6);
    float den = ((e0 + e1) + (e2 + e3)) + ((e4 + e5) + e6);
    float pos = fmaf(3.0f, e6, fmaf(2.0f, e5, e4));
    float neg = fmaf(3.0f, e0, fmaf(2.0f, e1, e2));
    return __fdividef(pos - neg, den);
}

// Load one K=7 group (7 x 256-bit), soft-argmax 8 lanes, store one 256-bit result.
__device__ __forceinline__ void group7_oct(const float* __restrict__ in,
                                           float* __restrict__ outp) {
    float v[K][8];
#pragma unroll
    for (int c = 0; c < K; c++) {
        ldg256_cs(in + (size_t)c * HW, v[c]);   // 7 front-batched LDG.E.256
    }
    float r[8];
#pragma unroll
    for (int l = 0; l < 8; l++) {
        r[l] = soft1(v[0][l], v[1][l], v[2][l], v[3][l],
                     v[4][l], v[5][l], v[6][l]);
    }
    stg256_cs(outp, r);
}

__global__ __launch_bounds__(128, 6)
void softargmax_kernel(const float* __restrict__ x, float* __restrict__ out) {
    int q = blockIdx.x * blockDim.x + threadIdx.x;   // oct id in [0, B*HWO)
    int b = q >> HWO_LOG;
    int s = q & (HWO - 1);

    const float* in = x + (size_t)b * C_IN * HW + (size_t)s * 8;
    float* ob = out + (size_t)b * 2 * HW + (size_t)s * 8;

    group7_oct(in, ob);                               // channels 0..6  -> out ch 0
    group7_oct(in + (size_t)K * HW, ob + HW);         // channels 7..13 -> out ch 1
}

extern "C" void kernel_launch(void* const* d_in, const int* in_sizes, int n_in,
                              void* d_out, int out_size) {
    const float* x = (const float*)d_in[0];
    float* out = (float*)d_out;

    const int total_octs = B * HWO;          // 524,288
    const int threads = 128;
    const int blocks = total_octs / threads; // 4096

    softargmax_kernel<<<blocks, threads>>>(x, out);
}